// round 12
// baseline (speedup 1.0000x reference)
#include <cuda_runtime.h>
#include <cuda_bf16.h>
#include <cstdint>

#define VOCAB 4
#define DIM   128
#define MAX_SEGS 8192
#define CHUNK 16               // tokens per thread
#define BLOCK 256
#define NCOMB 32               // last-N blocks perform the combine
#define FULL  0xFFFFFFFFu

// Per-segment histogram. Zeroed at load; combine blocks re-zero after
// consuming -> "all zero on entry" holds for every launch / graph replay.
__device__ int g_counts[MAX_SEGS * VOCAB];
__device__ unsigned int g_done;   // hist-finished ticket; reset each launch
__device__ unsigned int g_fin;    // combine-finished counter; reset each launch

// Flush from (n, ssum=Σt, s0=Σ(t&1), s3=Σ(t==3)).
__device__ __forceinline__ void flush_counts(int seg, int n, int ssum, int s0, int s3) {
    if (n == 0) return;
    int n3 = s3;
    int n1 = s0 - s3;
    int n2 = (ssum - s0 - 2 * s3) >> 1;
    int n0 = n - n1 - n2 - n3;
    int* b = &g_counts[seg * VOCAB];
    if (n0) atomicAdd(b + 0, n0);
    if (n1) atomicAdd(b + 1, n1);
    if (n2) atomicAdd(b + 2, n2);
    if (n3) atomicAdd(b + 3, n3);
}

__device__ __forceinline__ void dp4_accum(int4 tk, int& ssum, int& s0, int& s3) {
    unsigned a = __byte_perm((unsigned)tk.x, (unsigned)tk.y, 0x0040);
    unsigned b = __byte_perm((unsigned)tk.z, (unsigned)tk.w, 0x0040);
    unsigned p = __byte_perm(a, b, 0x5410);        // low bytes of 4 tokens
    unsigned u  = p >> 1;
    unsigned b0 = p & 0x01010101u;
    unsigned b3 = p & u & 0x01010101u;
    ssum = __dp4a((int)p,  0x01010101, ssum);
    s0   = __dp4a((int)b0, 0x01010101, s0);
    s3   = __dp4a((int)b3, 0x01010101, s3);
}

#define HIST_STEP(S, TK)                                        \
    do {                                                        \
        if ((S) != seg) {                                       \
            flush_counts(seg, n, ssum, s0, s3);                 \
            n = 0; ssum = 0; s0 = 0; s3 = 0; seg = (S);         \
        }                                                       \
        n++;                                                    \
        ssum += (TK);                                           \
        s0   += (TK) & 1;                                       \
        s3   += ((TK) == 3);                                    \
    } while (0)

__global__ void __launch_bounds__(BLOCK)
fused_kernel(const int* __restrict__ tokens,
             const int* __restrict__ segids,
             const float* __restrict__ emb,
             float* __restrict__ out,
             int T, int R) {
    __shared__ unsigned int s_ticket;

    const int tid  = threadIdx.x;
    const int lane = tid & 31;
    const int base = (blockIdx.x * BLOCK + tid) * CHUNK;

    // ================= Phase 1: histogram (proven R10 path) =================
    int seg = 0, n = 0, ssum = 0, s0 = 0, s3 = 0;

    if (base + CHUNK <= T) {
        const int4* t4 = (const int4*)(tokens + base);
        int  sA = __ldg(&segids[base]);
        int  sB = __ldg(&segids[base + CHUNK - 1]);
        int4 t0 = __ldg(&t4[0]), t1 = __ldg(&t4[1]),
             t2 = __ldg(&t4[2]), t3 = __ldg(&t4[3]);
        if (sA == sB) {
            dp4_accum(t0, ssum, s0, s3);
            dp4_accum(t1, ssum, s0, s3);
            dp4_accum(t2, ssum, s0, s3);
            dp4_accum(t3, ssum, s0, s3);
            seg = sA;
            n = CHUNK;
        } else {
            const int4* g4 = (const int4*)(segids + base);
            int4 g0 = __ldg(&g4[0]), g1 = __ldg(&g4[1]),
                 g2 = __ldg(&g4[2]), g3 = __ldg(&g4[3]);
            seg = g0.x;
            HIST_STEP(g0.x, t0.x); HIST_STEP(g0.y, t0.y);
            HIST_STEP(g0.z, t0.z); HIST_STEP(g0.w, t0.w);
            HIST_STEP(g1.x, t1.x); HIST_STEP(g1.y, t1.y);
            HIST_STEP(g1.z, t1.z); HIST_STEP(g1.w, t1.w);
            HIST_STEP(g2.x, t2.x); HIST_STEP(g2.y, t2.y);
            HIST_STEP(g2.z, t2.z); HIST_STEP(g2.w, t2.w);
            HIST_STEP(g3.x, t3.x); HIST_STEP(g3.y, t3.y);
            HIST_STEP(g3.z, t3.z); HIST_STEP(g3.w, t3.w);
        }
    } else if (base < T) {
        int end = min(T, base + CHUNK);
        seg = __ldg(&segids[base]);
        for (int i = base; i < end; i++) {
            int s = __ldg(&segids[i]);
            int t = __ldg(&tokens[i]);
            HIST_STEP(s, t);
        }
    }
    // out-of-range lanes carry (seg=0, n=0): contribute zeros below.

    // Group-aggregated flush: lanes sharing a segment reduce together.
    unsigned grp = __match_any_sync(FULL, seg);
    int gn    = (int)__reduce_add_sync(grp, (unsigned)n);
    int gssum = (int)__reduce_add_sync(grp, (unsigned)ssum);
    int gs0   = (int)__reduce_add_sync(grp, (unsigned)s0);
    int gs3   = (int)__reduce_add_sync(grp, (unsigned)s3);
    if (lane == (int)(__ffs(grp) - 1))
        flush_counts(seg, gn, gssum, gs0, gs3);

    // ================= Ticket: identify the last NCOMB blocks =================
    __syncthreads();
    if (tid == 0) {
        __threadfence();                       // order my REDs before ticket
        s_ticket = atomicAdd(&g_done, 1u);
    }
    __syncthreads();

    const unsigned int grid    = gridDim.x;
    const unsigned int ncomb   = (grid < NCOMB) ? grid : NCOMB;
    const unsigned int ticket  = s_ticket;
    if (ticket < grid - ncomb) return;         // 457 blocks exit immediately

    // ================= Phase 2: combine (last ncomb blocks) =================
    const unsigned int c = ticket - (grid - ncomb);   // 0..ncomb-1

    // Hist-independent preload while stragglers drain.
    const float4* e = (const float4*)emb;
    float4 e0 = __ldg(&e[0 * 32 + lane]);
    float4 e1 = __ldg(&e[1 * 32 + lane]);
    float4 e2 = __ldg(&e[2 * 32 + lane]);
    float4 e3 = __ldg(&e[3 * 32 + lane]);

    if (tid == 0) {
        while (*(volatile unsigned int*)&g_done < grid)
            __nanosleep(32);
        __threadfence();                       // acquire: see all blocks' REDs
    }
    __syncthreads();

    // Each combine block owns a contiguous 256-float4 slice; 1 elem/thread.
    const int total  = R * 32;                 // float4 elements
    const int stride = (int)ncomb * BLOCK;
    for (int i = (int)c * BLOCK + tid; i < total; i += stride) {
        int sg = i >> 5;
        int4 cc = *(const int4*)&g_counts[sg * VOCAB];
        float f0 = (float)cc.x, f1 = (float)cc.y,
              f2 = (float)cc.z, f3 = (float)cc.w;
        float inv = 1.0f / fmaxf(f0 + f1 + f2 + f3, 1.0f);
        float4 r;
        r.x = (f0 * e0.x + f1 * e1.x + f2 * e2.x + f3 * e3.x) * inv;
        r.y = (f0 * e0.y + f1 * e1.y + f2 * e2.y + f3 * e3.y) * inv;
        r.z = (f0 * e0.z + f1 * e1.z + f2 * e2.z + f3 * e3.z) * inv;
        r.w = (f0 * e0.w + f1 * e1.w + f2 * e2.w + f3 * e3.w) * inv;
        ((float4*)out)[i] = r;
        if ((i & 31) == 0)                     // zero each segment exactly once
            *(int4*)&g_counts[sg * VOCAB] = make_int4(0, 0, 0, 0);
    }

    // ================= Epilogue: last combine block resets tickets ===========
    __syncthreads();
    if (tid == 0) {
        __threadfence();
        unsigned int t = atomicAdd(&g_fin, 1u);
        if (t == ncomb - 1) {
            g_done = 0u;
            g_fin  = 0u;
            __threadfence();
        }
    }
}

extern "C" void kernel_launch(void* const* d_in, const int* in_sizes, int n_in,
                              void* d_out, int out_size) {
    const int* tokens = (const int*)d_in[0];
    const int* segids = (const int*)d_in[1];
    const float* emb  = (const float*)d_in[2];
    float* out        = (float*)d_out;

    int T = in_sizes[0];
    int R = out_size / DIM;

    int nchunks = (T + CHUNK - 1) / CHUNK;
    int grid = (nchunks + BLOCK - 1) / BLOCK;      // one chunk per thread (~489)
    if (grid < 1) grid = 1;

    fused_kernel<<<grid, BLOCK>>>(tokens, segids, emb, out, T, R);
}

// round 13
// speedup vs baseline: 1.1400x; 1.1400x over previous
#include <cuda_runtime.h>
#include <cuda_bf16.h>
#include <cstdint>

#define VOCAB 4
#define DIM   128
#define MAX_SEGS 8192
#define CHUNK 16               // tokens per thread
#define HBLOCK 512             // hist block size (fewer CTAs, same warps)
#define CBLOCK 256             // combine block size
#define FULL  0xFFFFFFFFu

// Per-segment, per-vocab histogram. Zeroed at load; combine_kernel re-zeros
// after consuming -> invariant "all zero on entry" holds every launch/replay.
__device__ int g_counts[MAX_SEGS * VOCAB];

// Flush from (n, ssum=Σt, s0=Σ(t&1), s3=Σ(t==3)).
__device__ __forceinline__ void flush_counts(int seg, int n, int ssum, int s0, int s3) {
    if (n == 0) return;
    int n3 = s3;
    int n1 = s0 - s3;
    int n2 = (ssum - s0 - 2 * s3) >> 1;
    int n0 = n - n1 - n2 - n3;
    int* b = &g_counts[seg * VOCAB];
    if (n0) atomicAdd(b + 0, n0);
    if (n1) atomicAdd(b + 1, n1);
    if (n2) atomicAdd(b + 2, n2);
    if (n3) atomicAdd(b + 3, n3);
}

// dp4a partial sums for 4 packed tokens (one int4 of token words).
__device__ __forceinline__ void dp4_accum(int4 tk, int& ssum, int& s0, int& s3) {
    unsigned a = __byte_perm((unsigned)tk.x, (unsigned)tk.y, 0x0040);
    unsigned b = __byte_perm((unsigned)tk.z, (unsigned)tk.w, 0x0040);
    unsigned p = __byte_perm(a, b, 0x5410);        // low bytes of 4 tokens
    unsigned u  = p >> 1;
    unsigned b0 = p & 0x01010101u;                 // t & 1
    unsigned b3 = p & u & 0x01010101u;             // t == 3
    ssum = __dp4a((int)p,  0x01010101, ssum);
    s0   = __dp4a((int)b0, 0x01010101, s0);
    s3   = __dp4a((int)b3, 0x01010101, s3);
}

#define HIST_STEP(S, TK)                                        \
    do {                                                        \
        if ((S) != seg) {                                       \
            flush_counts(seg, n, ssum, s0, s3);                 \
            n = 0; ssum = 0; s0 = 0; s3 = 0; seg = (S);         \
        }                                                       \
        n++;                                                    \
        ssum += (TK);                                           \
        s0   += (TK) & 1;                                       \
        s3   += ((TK) == 3);                                    \
    } while (0)

__global__ void __launch_bounds__(HBLOCK)
hist_kernel(const int* __restrict__ tokens,
            const int* __restrict__ segids,
            int T) {
    const int tid  = threadIdx.x;
    const int lane = tid & 31;
    const int base = (blockIdx.x * HBLOCK + tid) * CHUNK;

    // NO early return: all lanes join the warp collectives below.
    const bool fullchunk = (base + CHUNK <= T);

    // Shuffle-probe: ONE clamped scalar segid load per thread. Sorted ids =>
    // chunk [base, base+16) is uniform iff segids[base] == segids[base+16].
    // Neighbor lane's (clamped) load IS segids[base+16]; lane 31 loads it.
    int sA = __ldg(&segids[min(base, T - 1)]);
    int sNext = __shfl_down_sync(FULL, sA, 1);
    if (lane == 31)
        sNext = __ldg(&segids[min(base + CHUNK, T - 1)]);

    int seg = 0, n = 0, ssum = 0, s0 = 0, s3 = 0;

    if (fullchunk) {
        const int4* t4 = (const int4*)(tokens + base);
        int4 t0 = __ldg(&t4[0]), t1 = __ldg(&t4[1]),
             t2 = __ldg(&t4[2]), t3 = __ldg(&t4[3]);
        if (sA == sNext) {
            // fast path (~97%): whole chunk one segment, no segid vectors read
            dp4_accum(t0, ssum, s0, s3);
            dp4_accum(t1, ssum, s0, s3);
            dp4_accum(t2, ssum, s0, s3);
            dp4_accum(t3, ssum, s0, s3);
            seg = sA;
            n = CHUNK;
        } else {
            // boundary chunk: now fetch full segid vectors
            const int4* g4 = (const int4*)(segids + base);
            int4 g0 = __ldg(&g4[0]), g1 = __ldg(&g4[1]),
                 g2 = __ldg(&g4[2]), g3 = __ldg(&g4[3]);
            seg = g0.x;
            HIST_STEP(g0.x, t0.x); HIST_STEP(g0.y, t0.y);
            HIST_STEP(g0.z, t0.z); HIST_STEP(g0.w, t0.w);
            HIST_STEP(g1.x, t1.x); HIST_STEP(g1.y, t1.y);
            HIST_STEP(g1.z, t1.z); HIST_STEP(g1.w, t1.w);
            HIST_STEP(g2.x, t2.x); HIST_STEP(g2.y, t2.y);
            HIST_STEP(g2.z, t2.z); HIST_STEP(g2.w, t2.w);
            HIST_STEP(g3.x, t3.x); HIST_STEP(g3.y, t3.y);
            HIST_STEP(g3.z, t3.z); HIST_STEP(g3.w, t3.w);
        }
    } else if (base < T) {
        // tail chunk (scalar, bounds-checked)
        int end = min(T, base + CHUNK);
        seg = sA;                              // segids[base] (clamp is exact here)
        for (int i = base; i < end; i++) {
            int s = __ldg(&segids[i]);
            int t = __ldg(&tokens[i]);
            HIST_STEP(s, t);
        }
    }
    // fully out-of-range lanes carry (seg=0, n=0): contribute zeros below.

    // Group-aggregated flush: lanes sharing a segment reduce together.
    unsigned grp = __match_any_sync(FULL, seg);
    int gn    = (int)__reduce_add_sync(grp, (unsigned)n);
    int gssum = (int)__reduce_add_sync(grp, (unsigned)ssum);
    int gs0   = (int)__reduce_add_sync(grp, (unsigned)s0);
    int gs3   = (int)__reduce_add_sync(grp, (unsigned)s3);
    if (lane == (int)(__ffs(grp) - 1))
        flush_counts(seg, gn, gssum, gs0, gs3);
}

// ---------------------------------------------------------------------------
// Combine: warp per segment, float4 per lane; few CTAs (grid-stride safe).
// ---------------------------------------------------------------------------
__global__ void __launch_bounds__(CBLOCK)
combine_kernel(const float* __restrict__ emb,
               float* __restrict__ out, int R) {
    const int tid0   = blockIdx.x * CBLOCK + threadIdx.x;
    const int stride = gridDim.x * CBLOCK;
    const int lane   = threadIdx.x & 31;

    const float4* e = (const float4*)emb;
    float4 e0 = __ldg(&e[0 * 32 + lane]);
    float4 e1 = __ldg(&e[1 * 32 + lane]);
    float4 e2 = __ldg(&e[2 * 32 + lane]);
    float4 e3 = __ldg(&e[3 * 32 + lane]);

    const int total = R * 32;                  // float4 elements
    for (int i = tid0; i < total; i += stride) {
        int seg = i >> 5;                      // warp-uniform (stride % 32 == 0)
        int4 c = *(const int4*)&g_counts[seg * VOCAB];
        float f0 = (float)c.x, f1 = (float)c.y, f2 = (float)c.z, f3 = (float)c.w;
        float inv = 1.0f / fmaxf(f0 + f1 + f2 + f3, 1.0f);
        float4 r;
        r.x = (f0 * e0.x + f1 * e1.x + f2 * e2.x + f3 * e3.x) * inv;
        r.y = (f0 * e0.y + f1 * e1.y + f2 * e2.y + f3 * e3.y) * inv;
        r.z = (f0 * e0.z + f1 * e1.z + f2 * e2.z + f3 * e3.z) * inv;
        r.w = (f0 * e0.w + f1 * e1.w + f2 * e2.w + f3 * e3.w) * inv;
        ((float4*)out)[i] = r;

        __syncwarp();
        if ((i & 31) == 0)                     // restore zero invariant, once/seg
            *(int4*)&g_counts[seg * VOCAB] = make_int4(0, 0, 0, 0);
    }
}

extern "C" void kernel_launch(void* const* d_in, const int* in_sizes, int n_in,
                              void* d_out, int out_size) {
    const int* tokens = (const int*)d_in[0];
    const int* segids = (const int*)d_in[1];
    const float* emb  = (const float*)d_in[2];
    float* out        = (float*)d_out;

    int T = in_sizes[0];
    int R = out_size / DIM;

    int nchunks = (T + CHUNK - 1) / CHUNK;
    int grid = (nchunks + HBLOCK - 1) / HBLOCK;    // ~245 CTAs of 512
    if (grid < 1) grid = 1;
    hist_kernel<<<grid, HBLOCK>>>(tokens, segids, T);

    // 32 CTAs x 256 = 8192 threads >= R*32 = 8000 -> ~1 iteration per thread.
    combine_kernel<<<32, CBLOCK>>>(emb, out, R);
}

// round 14
// speedup vs baseline: 1.3810x; 1.2113x over previous
#include <cuda_runtime.h>
#include <cuda_bf16.h>
#include <cstdint>

#define VOCAB 4
#define DIM   128
#define MAX_SEGS 8192
#define CHUNK 16               // tokens per thread
#define HBLOCK 512             // hist block size (fewer CTAs, same warps)
#define CBLOCK 256             // combine block size
#define FULL  0xFFFFFFFFu

// Per-segment, per-vocab histogram. Zeroed at load; combine_kernel re-zeros
// after consuming -> invariant "all zero on entry" holds every launch/replay.
__device__ int g_counts[MAX_SEGS * VOCAB];

// Flush from (n, ssum=Σt, s0=Σ(t&1), s3=Σ(t==3)).
__device__ __forceinline__ void flush_counts(int seg, int n, int ssum, int s0, int s3) {
    if (n == 0) return;
    int n3 = s3;
    int n1 = s0 - s3;
    int n2 = (ssum - s0 - 2 * s3) >> 1;
    int n0 = n - n1 - n2 - n3;
    int* b = &g_counts[seg * VOCAB];
    if (n0) atomicAdd(b + 0, n0);
    if (n1) atomicAdd(b + 1, n1);
    if (n2) atomicAdd(b + 2, n2);
    if (n3) atomicAdd(b + 3, n3);
}

// dp4a partial sums for 4 packed tokens (one int4 of token words).
__device__ __forceinline__ void dp4_accum(int4 tk, int& ssum, int& s0, int& s3) {
    unsigned a = __byte_perm((unsigned)tk.x, (unsigned)tk.y, 0x0040);
    unsigned b = __byte_perm((unsigned)tk.z, (unsigned)tk.w, 0x0040);
    unsigned p = __byte_perm(a, b, 0x5410);        // low bytes of 4 tokens
    unsigned u  = p >> 1;
    unsigned b0 = p & 0x01010101u;                 // t & 1
    unsigned b3 = p & u & 0x01010101u;             // t == 3
    ssum = __dp4a((int)p,  0x01010101, ssum);
    s0   = __dp4a((int)b0, 0x01010101, s0);
    s3   = __dp4a((int)b3, 0x01010101, s3);
}

#define HIST_STEP(S, TK)                                        \
    do {                                                        \
        if ((S) != seg) {                                       \
            flush_counts(seg, n, ssum, s0, s3);                 \
            n = 0; ssum = 0; s0 = 0; s3 = 0; seg = (S);         \
        }                                                       \
        n++;                                                    \
        ssum += (TK);                                           \
        s0   += (TK) & 1;                                       \
        s3   += ((TK) == 3);                                    \
    } while (0)

__global__ void __launch_bounds__(HBLOCK)
hist_kernel(const int* __restrict__ tokens,
            const int* __restrict__ segids,
            int T) {
    const int tid  = threadIdx.x;
    const int lane = tid & 31;
    const int base = (blockIdx.x * HBLOCK + tid) * CHUNK;

    // NO early return: all lanes join the warp collectives below.
    const bool fullchunk = (base + CHUNK <= T);

    // Shuffle-probe: ONE clamped scalar segid load per thread. Sorted ids =>
    // chunk [base, base+16) is uniform iff segids[base] == segids[base+16].
    // Neighbor lane's (clamped) load IS segids[base+16]; lane 31 loads it.
    int sA = __ldg(&segids[min(base, T - 1)]);
    int sNext = __shfl_down_sync(FULL, sA, 1);
    if (lane == 31)
        sNext = __ldg(&segids[min(base + CHUNK, T - 1)]);

    int seg = 0, n = 0, ssum = 0, s0 = 0, s3 = 0;

    if (fullchunk) {
        const int4* t4 = (const int4*)(tokens + base);
        int4 t0 = __ldg(&t4[0]), t1 = __ldg(&t4[1]),
             t2 = __ldg(&t4[2]), t3 = __ldg(&t4[3]);
        if (sA == sNext) {
            // fast path (~97%): whole chunk one segment, no segid vectors read
            dp4_accum(t0, ssum, s0, s3);
            dp4_accum(t1, ssum, s0, s3);
            dp4_accum(t2, ssum, s0, s3);
            dp4_accum(t3, ssum, s0, s3);
            seg = sA;
            n = CHUNK;
        } else {
            // boundary chunk: now fetch full segid vectors
            const int4* g4 = (const int4*)(segids + base);
            int4 g0 = __ldg(&g4[0]), g1 = __ldg(&g4[1]),
                 g2 = __ldg(&g4[2]), g3 = __ldg(&g4[3]);
            seg = g0.x;
            HIST_STEP(g0.x, t0.x); HIST_STEP(g0.y, t0.y);
            HIST_STEP(g0.z, t0.z); HIST_STEP(g0.w, t0.w);
            HIST_STEP(g1.x, t1.x); HIST_STEP(g1.y, t1.y);
            HIST_STEP(g1.z, t1.z); HIST_STEP(g1.w, t1.w);
            HIST_STEP(g2.x, t2.x); HIST_STEP(g2.y, t2.y);
            HIST_STEP(g2.z, t2.z); HIST_STEP(g2.w, t2.w);
            HIST_STEP(g3.x, t3.x); HIST_STEP(g3.y, t3.y);
            HIST_STEP(g3.z, t3.z); HIST_STEP(g3.w, t3.w);
        }
    } else if (base < T) {
        // tail chunk (scalar, bounds-checked)
        int end = min(T, base + CHUNK);
        seg = sA;                              // segids[base] (clamp exact here)
        for (int i = base; i < end; i++) {
            int s = __ldg(&segids[i]);
            int t = __ldg(&tokens[i]);
            HIST_STEP(s, t);
        }
    }
    // fully out-of-range lanes carry (seg=0, n=0): contribute zeros below.

    // Group-aggregated flush: lanes sharing a segment reduce together.
    unsigned grp = __match_any_sync(FULL, seg);
    int gn    = (int)__reduce_add_sync(grp, (unsigned)n);
    int gssum = (int)__reduce_add_sync(grp, (unsigned)ssum);
    int gs0   = (int)__reduce_add_sync(grp, (unsigned)s0);
    int gs3   = (int)__reduce_add_sync(grp, (unsigned)s3);
    if (lane == (int)(__ffs(grp) - 1))
        flush_counts(seg, gn, gssum, gs0, gs3);
}

// ---------------------------------------------------------------------------
// Combine: one warp per segment, one float4 per lane (32 lanes x 4 = 128 dims).
// Wide launch (250 CTAs) — measured fastest shape for this kernel.
// ---------------------------------------------------------------------------
__global__ void __launch_bounds__(CBLOCK)
combine_kernel(const float* __restrict__ emb,
               float* __restrict__ out, int R) {
    int tid  = blockIdx.x * CBLOCK + threadIdx.x;
    int seg  = tid >> 5;
    int lane = tid & 31;
    if (seg >= R) return;

    // Counts first: L2 round-trip overlaps the 4 emb loads below.
    int4 c = *(const int4*)&g_counts[seg * VOCAB];

    const float4* e = (const float4*)emb;
    float4 e0 = __ldg(&e[0 * 32 + lane]);
    float4 e1 = __ldg(&e[1 * 32 + lane]);
    float4 e2 = __ldg(&e[2 * 32 + lane]);
    float4 e3 = __ldg(&e[3 * 32 + lane]);

    float f0 = (float)c.x, f1 = (float)c.y, f2 = (float)c.z, f3 = (float)c.w;
    float inv = 1.0f / fmaxf(f0 + f1 + f2 + f3, 1.0f);

    float4 r;
    r.x = (f0 * e0.x + f1 * e1.x + f2 * e2.x + f3 * e3.x) * inv;
    r.y = (f0 * e0.y + f1 * e1.y + f2 * e2.y + f3 * e3.y) * inv;
    r.z = (f0 * e0.z + f1 * e1.z + f2 * e2.z + f3 * e3.z) * inv;
    r.w = (f0 * e0.w + f1 * e1.w + f2 * e2.w + f3 * e3.w) * inv;
    ((float4*)out)[seg * 32 + lane] = r;

    // Restore zero invariant. No sync needed: this lane's read of g_counts
    // precedes in program order, and no other warp touches this segment.
    if (lane == 0)
        *(int4*)&g_counts[seg * VOCAB] = make_int4(0, 0, 0, 0);
}

extern "C" void kernel_launch(void* const* d_in, const int* in_sizes, int n_in,
                              void* d_out, int out_size) {
    const int* tokens = (const int*)d_in[0];
    const int* segids = (const int*)d_in[1];
    const float* emb  = (const float*)d_in[2];
    float* out        = (float*)d_out;

    int T = in_sizes[0];
    int R = out_size / DIM;

    int nchunks = (T + CHUNK - 1) / CHUNK;
    int grid = (nchunks + HBLOCK - 1) / HBLOCK;    // ~245 CTAs of 512
    if (grid < 1) grid = 1;
    hist_kernel<<<grid, HBLOCK>>>(tokens, segids, T);

    int cthreads = R * 32;
    int cgrid = (cthreads + CBLOCK - 1) / CBLOCK;  // ~250 CTAs of 256
    combine_kernel<<<cgrid, CBLOCK>>>(emb, out, R);
}

// round 15
// speedup vs baseline: 1.3851x; 1.0030x over previous
#include <cuda_runtime.h>
#include <cuda_bf16.h>
#include <cstdint>

#define VOCAB 4
#define DIM   128
#define MAX_SEGS 8192
#define CHUNK 16               // tokens per thread
#define HBLOCK 512             // hist block size (single wave: ~245 CTAs)
#define CBLOCK 256             // combine block size
#define FULL  0xFFFFFFFFu

// Per-segment, per-vocab histogram. Zeroed at load; combine_kernel re-zeros
// after consuming -> invariant "all zero on entry" holds every launch/replay.
__device__ int g_counts[MAX_SEGS * VOCAB];

// Flush from (n, ssum=Σt, s0=Σ(t&1), s3=Σ(t==3)).
__device__ __forceinline__ void flush_counts(int seg, int n, int ssum, int s0, int s3) {
    if (n == 0) return;
    int n3 = s3;
    int n1 = s0 - s3;
    int n2 = (ssum - s0 - 2 * s3) >> 1;
    int n0 = n - n1 - n2 - n3;
    int* b = &g_counts[seg * VOCAB];
    if (n0) atomicAdd(b + 0, n0);
    if (n1) atomicAdd(b + 1, n1);
    if (n2) atomicAdd(b + 2, n2);
    if (n3) atomicAdd(b + 3, n3);
}

// dp4a partial sums for 4 packed tokens (one int4 of token words).
__device__ __forceinline__ void dp4_accum(int4 tk, int& ssum, int& s0, int& s3) {
    unsigned a = __byte_perm((unsigned)tk.x, (unsigned)tk.y, 0x0040);
    unsigned b = __byte_perm((unsigned)tk.z, (unsigned)tk.w, 0x0040);
    unsigned p = __byte_perm(a, b, 0x5410);        // low bytes of 4 tokens
    unsigned u  = p >> 1;
    unsigned b0 = p & 0x01010101u;                 // t & 1
    unsigned b3 = p & u & 0x01010101u;             // t == 3
    ssum = __dp4a((int)p,  0x01010101, ssum);
    s0   = __dp4a((int)b0, 0x01010101, s0);
    s3   = __dp4a((int)b3, 0x01010101, s3);
}

#define HIST_STEP(S, TK)                                        \
    do {                                                        \
        if ((S) != seg) {                                       \
            flush_counts(seg, n, ssum, s0, s3);                 \
            n = 0; ssum = 0; s0 = 0; s3 = 0; seg = (S);         \
        }                                                       \
        n++;                                                    \
        ssum += (TK);                                           \
        s0   += (TK) & 1;                                       \
        s3   += ((TK) == 3);                                    \
    } while (0)

__global__ void __launch_bounds__(HBLOCK)
hist_kernel(const int* __restrict__ tokens,
            const int* __restrict__ segids,
            int T) {
    // Let the PDL-dependent combine grid begin launching/ramping immediately;
    // it gates on this grid's completion via cudaGridDependencySynchronize().
    cudaTriggerProgrammaticLaunchCompletion();

    const int tid  = threadIdx.x;
    const int lane = tid & 31;
    const int base = (blockIdx.x * HBLOCK + tid) * CHUNK;

    // NO early return: all lanes join the warp collectives below.
    const bool fullchunk = (base + CHUNK <= T);

    // Shuffle-probe: ONE clamped scalar segid load per thread. Sorted ids =>
    // chunk [base, base+16) is uniform iff segids[base] == segids[base+16].
    int sA = __ldg(&segids[min(base, T - 1)]);
    int sNext = __shfl_down_sync(FULL, sA, 1);
    if (lane == 31)
        sNext = __ldg(&segids[min(base + CHUNK, T - 1)]);

    int seg = 0, n = 0, ssum = 0, s0 = 0, s3 = 0;

    if (fullchunk) {
        const int4* t4 = (const int4*)(tokens + base);
        int4 t0 = __ldg(&t4[0]), t1 = __ldg(&t4[1]),
             t2 = __ldg(&t4[2]), t3 = __ldg(&t4[3]);
        if (sA == sNext) {
            // fast path (~97%): whole chunk one segment, no segid vectors read
            dp4_accum(t0, ssum, s0, s3);
            dp4_accum(t1, ssum, s0, s3);
            dp4_accum(t2, ssum, s0, s3);
            dp4_accum(t3, ssum, s0, s3);
            seg = sA;
            n = CHUNK;
        } else {
            // boundary chunk: now fetch full segid vectors
            const int4* g4 = (const int4*)(segids + base);
            int4 g0 = __ldg(&g4[0]), g1 = __ldg(&g4[1]),
                 g2 = __ldg(&g4[2]), g3 = __ldg(&g4[3]);
            seg = g0.x;
            HIST_STEP(g0.x, t0.x); HIST_STEP(g0.y, t0.y);
            HIST_STEP(g0.z, t0.z); HIST_STEP(g0.w, t0.w);
            HIST_STEP(g1.x, t1.x); HIST_STEP(g1.y, t1.y);
            HIST_STEP(g1.z, t1.z); HIST_STEP(g1.w, t1.w);
            HIST_STEP(g2.x, t2.x); HIST_STEP(g2.y, t2.y);
            HIST_STEP(g2.z, t2.z); HIST_STEP(g2.w, t2.w);
            HIST_STEP(g3.x, t3.x); HIST_STEP(g3.y, t3.y);
            HIST_STEP(g3.z, t3.z); HIST_STEP(g3.w, t3.w);
        }
    } else if (base < T) {
        // tail chunk (scalar, bounds-checked)
        int end = min(T, base + CHUNK);
        seg = sA;
        for (int i = base; i < end; i++) {
            int s = __ldg(&segids[i]);
            int t = __ldg(&tokens[i]);
            HIST_STEP(s, t);
        }
    }
    // fully out-of-range lanes carry (seg=0, n=0): contribute zeros below.

    // Group-aggregated flush: lanes sharing a segment reduce together.
    unsigned grp = __match_any_sync(FULL, seg);
    int gn    = (int)__reduce_add_sync(grp, (unsigned)n);
    int gssum = (int)__reduce_add_sync(grp, (unsigned)ssum);
    int gs0   = (int)__reduce_add_sync(grp, (unsigned)s0);
    int gs3   = (int)__reduce_add_sync(grp, (unsigned)s3);
    if (lane == (int)(__ffs(grp) - 1))
        flush_counts(seg, gn, gssum, gs0, gs3);
}

// ---------------------------------------------------------------------------
// Combine: one warp per segment, one float4 per lane. PDL-launched: becomes
// resident + loads emb WHILE hist runs (hist is a single wave with spare
// warp slots), then gates on hist completion before touching g_counts.
// ---------------------------------------------------------------------------
__global__ void __launch_bounds__(CBLOCK)
combine_kernel(const float* __restrict__ emb,
               float* __restrict__ out, int R) {
    int tid  = blockIdx.x * CBLOCK + threadIdx.x;
    int seg  = tid >> 5;
    int lane = tid & 31;

    // Hist-independent prologue: embedding rows into registers (overlapped
    // with the still-running hist grid).
    const float4* e = (const float4*)emb;
    float4 e0 = __ldg(&e[0 * 32 + lane]);
    float4 e1 = __ldg(&e[1 * 32 + lane]);
    float4 e2 = __ldg(&e[2 * 32 + lane]);
    float4 e3 = __ldg(&e[3 * 32 + lane]);

    // Gate: releases once the whole hist grid's memory is visible.
    cudaGridDependencySynchronize();

    if (seg >= R) return;

    int4 c = *(const int4*)&g_counts[seg * VOCAB];
    float f0 = (float)c.x, f1 = (float)c.y, f2 = (float)c.z, f3 = (float)c.w;
    float inv = 1.0f / fmaxf(f0 + f1 + f2 + f3, 1.0f);

    float4 r;
    r.x = (f0 * e0.x + f1 * e1.x + f2 * e2.x + f3 * e3.x) * inv;
    r.y = (f0 * e0.y + f1 * e1.y + f2 * e2.y + f3 * e3.y) * inv;
    r.z = (f0 * e0.z + f1 * e1.z + f2 * e2.z + f3 * e3.z) * inv;
    r.w = (f0 * e0.w + f1 * e1.w + f2 * e2.w + f3 * e3.w) * inv;
    ((float4*)out)[seg * 32 + lane] = r;

    // Restore zero invariant (no sync needed: per-lane program order, and
    // no other warp touches this segment's counters).
    if (lane == 0)
        *(int4*)&g_counts[seg * VOCAB] = make_int4(0, 0, 0, 0);
}

extern "C" void kernel_launch(void* const* d_in, const int* in_sizes, int n_in,
                              void* d_out, int out_size) {
    const int* tokens = (const int*)d_in[0];
    const int* segids = (const int*)d_in[1];
    const float* emb  = (const float*)d_in[2];
    float* out        = (float*)d_out;

    int T = in_sizes[0];
    int R = out_size / DIM;

    int nchunks = (T + CHUNK - 1) / CHUNK;
    int grid = (nchunks + HBLOCK - 1) / HBLOCK;    // ~245 CTAs: single wave
    if (grid < 1) grid = 1;
    hist_kernel<<<grid, HBLOCK>>>(tokens, segids, T);

    int cthreads = R * 32;
    int cgrid = (cthreads + CBLOCK - 1) / CBLOCK;  // ~250 CTAs of 256

    // PDL launch: combine ramps concurrently with hist; correctness gated
    // inside by cudaGridDependencySynchronize().
    cudaLaunchConfig_t cfg = {};
    cfg.gridDim  = dim3((unsigned)cgrid, 1, 1);
    cfg.blockDim = dim3(CBLOCK, 1, 1);
    cfg.dynamicSmemBytes = 0;
    cudaLaunchAttribute attr[1];
    attr[0].id = cudaLaunchAttributeProgrammaticStreamSerialization;
    attr[0].val.programmaticStreamSerializationAllowed = 1;
    cfg.attrs    = attr;
    cfg.numAttrs = 1;
    cudaLaunchKernelEx(&cfg, combine_kernel, emb, out, R);
}